// round 13
// baseline (speedup 1.0000x reference)
#include <cuda_runtime.h>
#include <cstdint>

// 3-level db4 wavedec (periodization) along axis 1 of (64, 4096, 64) fp32.
// Output rows: [cA3 (512) | cD3 (512) | cD2 (1024) | cD1 (2048)] x 64 feats.
//
// R13 (= R12 fixed): composite-filter direct form. Every output band is ONE
// convolution of x: cD1 = 8-tap/stride2, cD2 = 22-tap/stride4, cA3/cD3 =
// 50-tap/stride8. No shared memory, no __syncthreads, no inter-level
// dependency: warps stream global loads continuously. Taps are function-local
// constexpr (compile-time in device code) -> FFMA immediates.

#define NTHREADS 256

struct Taps {
    float d1[8];
    float d2[22];
    float a3[50];
    float d3[50];
};

__host__ __device__ constexpr Taps make_taps() {
    const double lo[8] = {
        -0.010597401784997278, 0.032883011666982945, 0.030841381835986965,
        -0.18703481171888114, -0.02798376941698385, 0.6308807679295904,
         0.7148465705525415,   0.23037781330885523 };
    double rlo[8] = {}, rhi[8] = {};
    for (int t = 0; t < 8; ++t) {
        rlo[t] = lo[7 - t];
        rhi[t] = (t % 2 == 0) ? lo[t] : -lo[t];
    }
    double g2a[22] = {}, g2d[22] = {};
    for (int s = 0; s < 8; ++s)
        for (int t = 0; t < 8; ++t) {
            g2a[2 * s + t] += rlo[s] * rlo[t];
            g2d[2 * s + t] += rhi[s] * rlo[t];
        }
    double g3a[50] = {}, g3d[50] = {};
    for (int w = 0; w < 8; ++w)
        for (int u = 0; u < 22; ++u) {
            g3a[4 * w + u] += rlo[w] * g2a[u];
            g3d[4 * w + u] += rhi[w] * g2a[u];
        }
    Taps T = {};
    for (int t = 0; t < 8; ++t)  T.d1[t] = (float)rhi[t];
    for (int t = 0; t < 22; ++t) T.d2[t] = (float)g2d[t];
    for (int t = 0; t < 50; ++t) { T.a3[t] = (float)g3a[t]; T.d3[t] = (float)g3d[t]; }
    return T;
}

__device__ __forceinline__ void fma4(float4& acc, const float4 w, const float c) {
    acc.x = fmaf(w.x, c, acc.x);
    acc.y = fmaf(w.y, c, acc.y);
    acc.z = fmaf(w.z, c, acc.z);
    acc.w = fmaf(w.w, c, acc.w);
}

// CTA type layout on blockIdx.x (long tasks first for tail shaping):
//   x in [0,8)   : c3  (cA3+cD3), 16 groups of 4 outputs  -> j = x*16+grp in [0,128)
//   x in [8,16)  : cD2,           16 groups of 8 outputs  -> j in [0,128)
//   x in [16,32) : cD1,           16 groups of 8 outputs  -> j in [0,256)
__global__ void __launch_bounds__(NTHREADS, 2)
wavedec_kernel(const float* __restrict__ x, float* __restrict__ out) {
    constexpr Taps TAPS = make_taps();

    const int tid  = threadIdx.x;
    const int lane = tid & 15;    // float4 feature lane (64 floats = 16 float4)
    const int grp  = tid >> 4;    // 0..15
    const int bx   = blockIdx.x;  // 0..31
    const int b    = blockIdx.y;  // 0..63

    const float4* __restrict__ xb =
        reinterpret_cast<const float4*>(x + (size_t)b * 4096 * 64);
    float4* __restrict__ ob =
        reinterpret_cast<float4*>(out + (size_t)b * 4096 * 64);

    if (bx < 8) {
        // ---- cA3 + cD3: 50-tap filters, stride 8, 4 outputs per group ----
        const int j    = bx * 16 + grp;       // [0,128)
        const int k0   = 4 * j;               // output base
        const int base = 8 * k0 - 42;         // window rows base..base+73
        const bool wrap = (base < 0);
        const float4* p = xb + (size_t)(wrap ? 0 : base) * 16 + lane;

        float4 aA[4] = {}, aD[4] = {};
#pragma unroll
        for (int c = 0; c < 74; c += 10) {
            const int cnt = (c < 70) ? 10 : 4;
            float4 w[10];
            if (!wrap) {
#pragma unroll
                for (int r = 0; r < 10; ++r)
                    if (r < cnt) w[r] = p[(c + r) * 16];
            } else {
#pragma unroll
                for (int r = 0; r < 10; ++r)
                    if (r < cnt) w[r] = xb[(size_t)((base + c + r + 4096) & 4095) * 16 + lane];
            }
#pragma unroll
            for (int r = 0; r < 10; ++r) {
                if (r < cnt) {
                    const int R = c + r;
#pragma unroll
                    for (int q = 0; q < 4; ++q) {
                        const int tt = R - 8 * q;
                        if (tt >= 0 && tt < 50) {
                            fma4(aA[q], w[r], TAPS.a3[tt]);
                            fma4(aD[q], w[r], TAPS.d3[tt]);
                        }
                    }
                }
            }
        }
#pragma unroll
        for (int q = 0; q < 4; ++q) {
            ob[(size_t)(k0 + q) * 16 + lane]       = aA[q];
            ob[(size_t)(512 + k0 + q) * 16 + lane] = aD[q];
        }
    } else if (bx < 16) {
        // ---- cD2: 22-tap filter, stride 4, 8 outputs per group ----
        const int j    = (bx - 8) * 16 + grp; // [0,128)
        const int k0   = 8 * j;
        const int base = 4 * k0 - 18;         // window rows base..base+49
        const bool wrap = (base < 0);
        const float4* p = xb + (size_t)(wrap ? 0 : base) * 16 + lane;

        float4 acc[8] = {};
#pragma unroll
        for (int c = 0; c < 50; c += 10) {
            float4 w[10];
            if (!wrap) {
#pragma unroll
                for (int r = 0; r < 10; ++r)
                    w[r] = p[(c + r) * 16];
            } else {
#pragma unroll
                for (int r = 0; r < 10; ++r)
                    w[r] = xb[(size_t)((base + c + r + 4096) & 4095) * 16 + lane];
            }
#pragma unroll
            for (int r = 0; r < 10; ++r) {
                const int R = c + r;
#pragma unroll
                for (int q = 0; q < 8; ++q) {
                    const int tt = R - 4 * q;
                    if (tt >= 0 && tt < 22)
                        fma4(acc[q], w[r], TAPS.d2[tt]);
                }
            }
        }
#pragma unroll
        for (int q = 0; q < 8; ++q)
            ob[(size_t)(1024 + k0 + q) * 16 + lane] = acc[q];
    } else {
        // ---- cD1: 8-tap filter, stride 2, 8 outputs per group ----
        const int j    = (bx - 16) * 16 + grp; // [0,256)
        const int k0   = 8 * j;
        const int base = 2 * k0 - 6;           // window rows base..base+21
        const bool wrap = (base < 0);
        const float4* p = xb + (size_t)(wrap ? 0 : base) * 16 + lane;

        float4 acc[8] = {};
#pragma unroll
        for (int c = 0; c < 22; c += 11) {
            float4 w[11];
            if (!wrap) {
#pragma unroll
                for (int r = 0; r < 11; ++r)
                    w[r] = p[(c + r) * 16];
            } else {
#pragma unroll
                for (int r = 0; r < 11; ++r)
                    w[r] = xb[(size_t)((base + c + r + 4096) & 4095) * 16 + lane];
            }
#pragma unroll
            for (int r = 0; r < 11; ++r) {
                const int R = c + r;
#pragma unroll
                for (int q = 0; q < 8; ++q) {
                    const int tt = R - 2 * q;
                    if (tt >= 0 && tt < 8)
                        fma4(acc[q], w[r], TAPS.d1[tt]);
                }
            }
        }
#pragma unroll
        for (int q = 0; q < 8; ++q)
            ob[(size_t)(2048 + k0 + q) * 16 + lane] = acc[q];
    }
}

extern "C" void kernel_launch(void* const* d_in, const int* in_sizes, int n_in,
                              void* d_out, int out_size) {
    const float* x = (const float*)d_in[0];
    float* out = (float*)d_out;
    dim3 grid(32, 64);
    wavedec_kernel<<<grid, NTHREADS>>>(x, out);
}

// round 14
// speedup vs baseline: 1.2994x; 1.2994x over previous
#include <cuda_runtime.h>
#include <cstdint>

// 3-level db4 wavedec (periodization) along axis 1 of (64, 4096, 64) fp32.
// Output rows: [cA3 (512) | cD3 (512) | cD2 (1024) | cD1 (2048)] x 64 feats.
//
// R14: R6 compute core (batched 14-row windows, packed f32x2 FMA, 128-bit
// memory ops, detail filter via RHI[t]=s(t)*RLO[7-t]) plus cache-policy
// hints: ld.global.nc for x (read-only), st.global.cs for all output
// (evict-first streaming) so the 64MB input stays L2-resident across graph
// replays instead of being evicted by output write allocation.

#define NTHREADS 256
#define A1_ROWS  82   // valid local cA1 rows
#define A2_ROWS  38   // valid local cA2 rows
#define A1_CAP   86   // level-2 batched reads reach row 85
#define A2_CAP   40

__device__ __forceinline__ void fma2(unsigned long long& acc,
                                     unsigned long long w,
                                     unsigned long long c) {
    asm("fma.rn.f32x2 %0, %1, %2, %0;" : "+l"(acc) : "l"(w), "l"(c));
}

__device__ __forceinline__ unsigned long long pneg(unsigned long long v) {
    return v ^ 0x8000000080000000ull;
}

__device__ __forceinline__ ulonglong2 ldg_nc(const ulonglong2* p) {
    ulonglong2 r;
    asm("ld.global.nc.v2.u64 {%0, %1}, [%2];"
        : "=l"(r.x), "=l"(r.y) : "l"(p));
    return r;
}

__device__ __forceinline__ void stg_cs(ulonglong2* p,
                                       unsigned long long a,
                                       unsigned long long b) {
    asm volatile("st.global.cs.v2.u64 [%0], {%1, %2};"
                 :: "l"(p), "l"(a), "l"(b) : "memory");
}

// consume batched window v[14] into 4-row accumulators:
// a[q] += v[2q+t]*RLO[t];  d[q] += s(t)*v[2q+t]*RLO[7-t]
#define CONSUME_WINDOW                                              \
    _Pragma("unroll")                                               \
    for (int t = 0; t < 14; ++t) {                                  \
        const unsigned long long WL = v[t].x, WH = v[t].y;          \
        const unsigned long long nWL = (t & 1) ? pneg(WL) : WL;     \
        const unsigned long long nWH = (t & 1) ? pneg(WH) : WH;     \
        _Pragma("unroll")                                           \
        for (int q = 0; q < 4; ++q) {                               \
            const int tt = t - 2 * q;                               \
            if (tt >= 0 && tt < 8) {                                \
                fma2(aL[q], WL, clo[tt]);                           \
                fma2(aH[q], WH, clo[tt]);                           \
                fma2(dL[q], nWL, clo[7 - tt]);                      \
                fma2(dH[q], nWH, clo[7 - tt]);                      \
            }                                                       \
        }                                                           \
    }

__global__ void __launch_bounds__(NTHREADS, 3)
wavedec_kernel(const float* __restrict__ x, float* __restrict__ out) {
    __shared__ ulonglong2 s_a1[A1_CAP * 16];
    __shared__ ulonglong2 s_a2[A2_CAP * 16];

    const int tid  = threadIdx.x;
    const int f4   = tid & 15;    // float4 feature lane (64 floats = 16 float4)
    const int grp  = tid >> 4;    // 0..15, each group: 4 consecutive rows/pass
    const int tile = blockIdx.x;  // 0..31
    const int b    = blockIdx.y;  // 0..63

    // Reversed approx filter: out_a[i] = sum_t src[2i+t] * RLO[t]
    const float RLO[8] = {
         0.23037781330885523f,  0.7148465705525415f,   0.6308807679295904f,
        -0.02798376941698385f, -0.18703481171888114f,  0.030841381835986965f,
         0.032883011666982945f, -0.010597401784997278f };

    unsigned long long clo[8];
#pragma unroll
    for (int t = 0; t < 8; ++t)
        clo[t] = (unsigned long long)__float_as_uint(RLO[t]) * 0x100000001ull;

    const ulonglong2* __restrict__ xb4 =
        reinterpret_cast<const ulonglong2*>(x + (size_t)b * 4096 * 64);
    ulonglong2* __restrict__ ob4 =
        reinterpret_cast<ulonglong2*>(out + (size_t)b * 4096 * 64);

    const int g0 = 128 * tile - 42;  // global x row of local window origin

    // ---- Level 1: x (global) -> cA1 (smem) + cD1 (global) ----
#pragma unroll
    for (int pass = 0; pass < 2; ++pass) {
        const int i0 = pass * 64 + grp * 4;
        if (i0 < A1_ROWS) {
            unsigned long long aL[4] = {}, aH[4] = {}, dL[4] = {}, dH[4] = {};
            ulonglong2 v[14];
            const int r0 = g0 + 2 * i0;
            if (r0 >= 0 && r0 <= 4096 - 14) {
                const ulonglong2* p = xb4 + (size_t)r0 * 16 + f4;
#pragma unroll
                for (int t = 0; t < 14; ++t)
                    v[t] = ldg_nc(p + t * 16);
            } else {
#pragma unroll
                for (int t = 0; t < 14; ++t) {
                    const int r = (r0 + t + 4096) & 4095;
                    v[t] = ldg_nc(xb4 + (size_t)r * 16 + f4);
                }
            }
            CONSUME_WINDOW
#pragma unroll
            for (int q = 0; q < 4; ++q) {
                const int i = i0 + q;          // max 83 < A1_CAP
                s_a1[i * 16 + f4] = make_ulonglong2(aL[q], aH[q]);
                if (i >= 18 && i < A1_ROWS)
                    stg_cs(ob4 + (size_t)(2048 + 64 * tile + (i - 18)) * 16 + f4,
                           dL[q], dH[q]);
            }
        }
    }
    __syncthreads();

    // ---- Level 2: cA1 (smem) -> cA2 (smem) + cD2 (global) ----
    {
        const int i0 = grp * 4;
        if (i0 < A2_ROWS) {
            unsigned long long aL[4] = {}, aH[4] = {}, dL[4] = {}, dH[4] = {};
            ulonglong2 v[14];
            const ulonglong2* p = s_a1 + (size_t)(2 * i0) * 16 + f4;
#pragma unroll
            for (int t = 0; t < 14; ++t)
                v[t] = p[t * 16];
            CONSUME_WINDOW
#pragma unroll
            for (int q = 0; q < 4; ++q) {
                const int i = i0 + q;          // max 39 < A2_CAP
                s_a2[i * 16 + f4] = make_ulonglong2(aL[q], aH[q]);
                if (i >= 6 && i < A2_ROWS)
                    stg_cs(ob4 + (size_t)(1024 + 32 * tile + (i - 6)) * 16 + f4,
                           dL[q], dH[q]);
            }
        }
    }
    __syncthreads();

    // ---- Level 3: cA2 (smem) -> cA3 + cD3 (global) ----
    {
        const int i0 = grp * 4;
        if (i0 < 16) {
            unsigned long long aL[4] = {}, aH[4] = {}, dL[4] = {}, dH[4] = {};
            ulonglong2 v[14];
            const ulonglong2* p = s_a2 + (size_t)(2 * i0) * 16 + f4;
#pragma unroll
            for (int t = 0; t < 14; ++t)
                v[t] = p[t * 16];
            CONSUME_WINDOW
#pragma unroll
            for (int q = 0; q < 4; ++q) {
                const int i = i0 + q;
                stg_cs(ob4 + (size_t)(16 * tile + i) * 16 + f4, aL[q], aH[q]);
                stg_cs(ob4 + (size_t)(512 + 16 * tile + i) * 16 + f4, dL[q], dH[q]);
            }
        }
    }
}

extern "C" void kernel_launch(void* const* d_in, const int* in_sizes, int n_in,
                              void* d_out, int out_size) {
    const float* x = (const float*)d_in[0];
    float* out = (float*)d_out;
    dim3 grid(32, 64);
    wavedec_kernel<<<grid, NTHREADS>>>(x, out);
}